// round 3
// baseline (speedup 1.0000x reference)
#include <cuda_runtime.h>
#include <cuda_bf16.h>

#define B 4
#define L 512
#define D 128
#define ROWS 8           // queries per block
#define KR (ROWS + 2)    // k rows incl. halo
#define EPSV 1e-8f

// accurate tanh: 1 - 2/(e^{2x}+1)
__device__ __forceinline__ float tanh_acc(float x) {
    float e2 = __expf(2.0f * x);
    return 1.0f - __fdividef(2.0f, e2 + 1.0f);
}

// ---------------------------------------------------------------------------
// Fully fused: per block of 8 queries, compute q (8 rows) and k (10 rows,
// halo) from X in SMEM, then window softmax + output. No global scratch.
// grid: (L/ROWS, B) = (64, 4); 128 threads
// ---------------------------------------------------------------------------
__global__ __launch_bounds__(128) void fused_kernel(
    const float* __restrict__ X,  const float* __restrict__ Wt,
    const float* __restrict__ Wx, const float* __restrict__ Wa,
    const float* __restrict__ bh, const float* __restrict__ ba_p,
    float* __restrict__ out)
{
    __shared__ float Xs[KR][D];     // X rows q0-1 .. q0+ROWS (clamped)
    __shared__ float qs[ROWS][D];   // q + bh
    __shared__ float ks[KR][D];     // k

    const int b   = blockIdx.y;
    const int q0  = blockIdx.x * ROWS;
    const int tid = threadIdx.x;
    const float* XB = X + b * L * D;

    // ---- load X tile (rows clamped at batch edge; masked later) ----
    #pragma unroll
    for (int i = tid; i < KR * (D / 4); i += 128) {
        int r = i >> 5, d4 = i & 31;
        int row = min(max(q0 - 1 + r, 0), L - 1);
        ((float4*)&Xs[r][0])[d4] = ((const float4*)(XB + row * D))[d4];
    }
    __syncthreads();

    // ---- mini-GEMM: thread c computes column c of q (8 rows) and k (10 rows)
    const int c = tid;
    float accq[ROWS], acck[KR];
    #pragma unroll
    for (int r = 0; r < ROWS; r++) accq[r] = 0.f;
    #pragma unroll
    for (int r = 0; r < KR; r++)   acck[r] = 0.f;

    const float* wtp = Wt + c;
    const float* wxp = Wx + c;
    #pragma unroll 4
    for (int d = 0; d < D; d++) {
        float wt = wtp[d * D];
        float wx = wxp[d * D];
        float x[KR];
        #pragma unroll
        for (int r = 0; r < KR; r++) x[r] = Xs[r][d];     // broadcast LDS
        #pragma unroll
        for (int r = 0; r < KR; r++)   acck[r] = fmaf(x[r],     wx, acck[r]);
        #pragma unroll
        for (int r = 0; r < ROWS; r++) accq[r] = fmaf(x[r + 1], wt, accq[r]);
    }

    const float bhc = bh[c];
    #pragma unroll
    for (int r = 0; r < ROWS; r++) qs[r][c] = accq[r] + bhc;
    #pragma unroll
    for (int r = 0; r < KR; r++)   ks[r][c] = acck[r];
    __syncthreads();

    // ---- window phase: 4 warps x 2 queries each ----
    const int warp = tid >> 5;
    const int lane = tid & 31;
    const float4 wv = ((const float4*)Wa)[lane];
    const float bav = ba_p[0];

    #pragma unroll
    for (int qq = 0; qq < 2; qq++) {
        const int rq = warp * 2 + qq;       // row in qs
        const int qi = q0 + rq;             // global query index
        float4 qv = ((const float4*)&qs[rq][0])[lane];

        float e[3];
        #pragma unroll
        for (int tt = 0; tt < 3; tt++) {
            int j = qi - 1 + tt;            // global key index
            float4 kv = ((const float4*)&ks[rq + tt][0])[lane];
            float p = tanh_acc(qv.x + kv.x) * wv.x
                    + tanh_acc(qv.y + kv.y) * wv.y
                    + tanh_acc(qv.z + kv.z) * wv.z
                    + tanh_acc(qv.w + kv.w) * wv.w;
            #pragma unroll
            for (int o = 16; o > 0; o >>= 1)
                p += __shfl_xor_sync(0xffffffffu, p, o);
            e[tt] = (j >= 0 && j < L) ? (p + bav) : -1e30f;
        }

        float m  = fmaxf(e[0], fmaxf(e[1], e[2]));
        float w0 = __expf(e[0] - m);
        float w1 = __expf(e[1] - m);
        float w2 = __expf(e[2] - m);
        float inv = __fdividef(1.0f, w0 + w1 + w2 + EPSV);

        float4 o4 = make_float4(0.f, 0.f, 0.f, 0.f);
        #pragma unroll
        for (int tt = 0; tt < 3; tt++) {
            float w = (tt == 0) ? w0 : (tt == 1) ? w1 : w2;
            float a = w * inv;
            float4 xv = ((const float4*)&Xs[rq + tt][0])[lane];
            o4.x = fmaf(a, xv.x, o4.x);
            o4.y = fmaf(a, xv.y, o4.y);
            o4.z = fmaf(a, xv.z, o4.z);
            o4.w = fmaf(a, xv.w, o4.w);
        }
        ((float4*)(out + (b * L + qi) * D))[lane] = o4;
    }
}

extern "C" void kernel_launch(void* const* d_in, const int* in_sizes, int n_in,
                              void* d_out, int out_size)
{
    const float* X  = (const float*)d_in[0];
    const float* Wt = (const float*)d_in[1];
    const float* Wx = (const float*)d_in[2];
    const float* Wa = (const float*)d_in[3];
    const float* bh = (const float*)d_in[4];
    const float* ba = (const float*)d_in[5];
    float* out = (float*)d_out;

    dim3 grid(L / ROWS, B);
    fused_kernel<<<grid, 128>>>(X, Wt, Wx, Wa, bh, ba, out);
}

// round 4
// speedup vs baseline: 1.3907x; 1.3907x over previous
#include <cuda_runtime.h>
#include <cuda_bf16.h>

#define B 4
#define L 512
#define D 128
#define ROWS 8           // queries per block
#define KR (ROWS + 2)    // k rows incl. halo
#define XT 12            // padded transposed row length (16B-aligned)
#define EPSV 1e-8f

// accurate tanh: 1 - 2/(e^{2x}+1)
__device__ __forceinline__ float tanh_acc(float x) {
    float e2 = __expf(2.0f * x);
    return 1.0f - __fdividef(2.0f, e2 + 1.0f);
}

// GEMM inner loops for one thread computing one output column over NR rows
// starting at smem-transposed row offset R0. w-prefetch depth 8.
template<int NR, int R0>
__device__ __forceinline__ void col_gemm(
    const float* __restrict__ wp,                 // &W[0*D + c]
    const float (*XsT)[XT], float* acc)
{
    #pragma unroll
    for (int r = 0; r < NR; r++) acc[r] = 0.f;

    for (int d0 = 0; d0 < D; d0 += 8) {
        float w[8];
        #pragma unroll
        for (int j = 0; j < 8; j++) w[j] = wp[(d0 + j) * D];   // 8 LDGs in flight
        #pragma unroll
        for (int j = 0; j < 8; j++) {
            const int d = d0 + j;
            float4 xa = *(const float4*)&XsT[d][0];
            float4 xb = *(const float4*)&XsT[d][4];
            float4 xc = *(const float4*)&XsT[d][8];
            float x[12] = {xa.x, xa.y, xa.z, xa.w,
                           xb.x, xb.y, xb.z, xb.w,
                           xc.x, xc.y, xc.z, xc.w};
            #pragma unroll
            for (int r = 0; r < NR; r++)
                acc[r] = fmaf(x[R0 + r], w[j], acc[r]);
        }
    }
}

// ---------------------------------------------------------------------------
// Fully fused: per block of 8 queries, compute q (8 rows) and k (10 rows
// incl. halo) from X, then window softmax + output. No global scratch.
// grid: (L/ROWS, B) = (64, 4); 256 threads (warps 0-3: q cols, 4-7: k cols)
// ---------------------------------------------------------------------------
__global__ __launch_bounds__(256) void fused_kernel(
    const float* __restrict__ X,  const float* __restrict__ Wt,
    const float* __restrict__ Wx, const float* __restrict__ Wa,
    const float* __restrict__ bh, const float* __restrict__ ba_p,
    float* __restrict__ out)
{
    __shared__ float Xs [KR][D];    // row-major (for output phase)
    __shared__ float XsT[D][XT];    // transposed (for GEMM broadcast reads)
    __shared__ float qs [ROWS][D];  // q + bh
    __shared__ float ks [KR][D];    // k

    const int b   = blockIdx.y;
    const int q0  = blockIdx.x * ROWS;
    const int tid = threadIdx.x;
    const float* XB = X + b * L * D;

    // ---- load X tile (rows clamped at batch edge; masked later), both layouts
    #pragma unroll
    for (int i = tid; i < KR * (D / 4); i += 256) {
        int r = i >> 5, d4 = i & 31;
        int row = min(max(q0 - 1 + r, 0), L - 1);
        float4 v = ((const float4*)(XB + row * D))[d4];
        ((float4*)&Xs[r][0])[d4] = v;
        XsT[d4 * 4 + 0][r] = v.x;
        XsT[d4 * 4 + 1][r] = v.y;
        XsT[d4 * 4 + 2][r] = v.z;
        XsT[d4 * 4 + 3][r] = v.w;
    }
    __syncthreads();

    // ---- mini-GEMMs: warps 0-3 -> q (rows 1..8), warps 4-7 -> k (rows 0..9)
    const int c = tid & 127;
    if (tid < 128) {
        float acc[ROWS];
        col_gemm<ROWS, 1>(Wt + c, XsT, acc);
        const float bhc = bh[c];
        #pragma unroll
        for (int r = 0; r < ROWS; r++) qs[r][c] = acc[r] + bhc;
    } else {
        float acc[KR];
        col_gemm<KR, 0>(Wx + c, XsT, acc);
        #pragma unroll
        for (int r = 0; r < KR; r++) ks[r][c] = acc[r];
    }
    __syncthreads();

    // ---- window phase: warp == query (8 warps, 8 queries) ----
    const int rq   = tid >> 5;          // query row in tile
    const int lane = tid & 31;
    const int qi   = q0 + rq;
    const float4 wv = ((const float4*)Wa)[lane];
    const float bav = ba_p[0];
    const float4 qv = ((const float4*)&qs[rq][0])[lane];

    float e[3];
    #pragma unroll
    for (int tt = 0; tt < 3; tt++) {
        int j = qi - 1 + tt;
        float4 kv = ((const float4*)&ks[rq + tt][0])[lane];
        float p = tanh_acc(qv.x + kv.x) * wv.x
                + tanh_acc(qv.y + kv.y) * wv.y
                + tanh_acc(qv.z + kv.z) * wv.z
                + tanh_acc(qv.w + kv.w) * wv.w;
        #pragma unroll
        for (int o = 16; o > 0; o >>= 1)
            p += __shfl_xor_sync(0xffffffffu, p, o);
        e[tt] = (j >= 0 && j < L) ? (p + bav) : -1e30f;
    }

    float m  = fmaxf(e[0], fmaxf(e[1], e[2]));
    float w0 = __expf(e[0] - m);
    float w1 = __expf(e[1] - m);
    float w2 = __expf(e[2] - m);
    float inv = __fdividef(1.0f, w0 + w1 + w2 + EPSV);

    float4 o4 = make_float4(0.f, 0.f, 0.f, 0.f);
    #pragma unroll
    for (int tt = 0; tt < 3; tt++) {
        float w = (tt == 0) ? w0 : (tt == 1) ? w1 : w2;
        float a = w * inv;
        float4 xv = ((const float4*)&Xs[rq + tt][0])[lane];
        o4.x = fmaf(a, xv.x, o4.x);
        o4.y = fmaf(a, xv.y, o4.y);
        o4.z = fmaf(a, xv.z, o4.z);
        o4.w = fmaf(a, xv.w, o4.w);
    }
    ((float4*)(out + (b * L + qi) * D))[lane] = o4;
}

extern "C" void kernel_launch(void* const* d_in, const int* in_sizes, int n_in,
                              void* d_out, int out_size)
{
    const float* X  = (const float*)d_in[0];
    const float* Wt = (const float*)d_in[1];
    const float* Wx = (const float*)d_in[2];
    const float* Wa = (const float*)d_in[3];
    const float* bh = (const float*)d_in[4];
    const float* ba = (const float*)d_in[5];
    float* out = (float*)d_out;

    dim3 grid(L / ROWS, B);
    fused_kernel<<<grid, 256>>>(X, Wt, Wx, Wa, bh, ba, out);
}